// round 14
// baseline (speedup 1.0000x reference)
#include <cuda_runtime.h>
#include <cuda_bf16.h>
#include <cuda_fp16.h>
#include <stdint.h>
#include <math.h>

#define NN 65536
#define NE 524288
#define EX (NE + NN)
#define DD 128
#define PK 136   // padded k-dim (bf16 elems); 272B rows => ldmatrix conflict-free

// ---------------- scratch (device globals: allocation-free) ----------------
__device__ __half g_hh[(size_t)NN * DD];    // 16MB: h in fp16 (agg gather path)
__device__ float g_x[(size_t)NN * DD];      // 32MB: layer activations
__device__ float g_as[NN];
__device__ float g_ad[NN];
__device__ int4  g_epk4[EX];                // packed (src, s0, s1, s2) per CSR slot
__device__ int   g_rowptr[NN + 1];
__device__ int   g_wslot[NN];
__device__ int   g_cnt[NN];
__device__ int   g_bsum[256];
__device__ float g_ve[3][32];
__device__ __nv_bfloat16 g_wh[3][DD * DD];   // W^T split hi (n-major)
__device__ __nv_bfloat16 g_wl[3][DD * DD];   // W^T split lo (n-major)

__device__ __forceinline__ float gelu_f(float x) {
    return 0.5f * x * (1.0f + erff(x * 0.7071067811865476f));
}

// ---------------- preprocessing ----------------
__global__ void k_wsplit(const float* __restrict__ Ws,
                         const float* __restrict__ We, const float* __restrict__ ae) {
    int b = blockIdx.x;
    if (b >= 193) {
        int i = (b - 193) * 256 + threadIdx.x;
        if (i < NN) g_cnt[i] = 0;
        if (i < 256) g_bsum[i] = 0;
        return;
    }
    if (b == 192) {
        int t = threadIdx.x;
        if (t < 96) {
            int l = t / 32, k = t % 32;
            const float* w = We + l * 32 * DD + k * DD;
            const float* a = ae + l * DD;
            float s = 0.f;
            #pragma unroll 8
            for (int d = 0; d < DD; d++) s += w[d] * a[d];
            g_ve[l][k] = s;
        }
        return;
    }
    int idx = b * blockDim.x + threadIdx.x;   // 3*128*128
    int l = idx >> 14;
    int rem = idx & 16383;
    int k = rem >> 7, n = rem & 127;
    float v = Ws[idx];
    __nv_bfloat16 h = __float2bfloat16_rn(v);
    float lo = v - __bfloat162float(h);
    g_wh[l][n * DD + k] = h;
    g_wl[l][n * DD + k] = __float2bfloat16_rn(lo);
}

__global__ void k_hist(const int* __restrict__ ei) {
    int e = blockIdx.x * blockDim.x + threadIdx.x;
    if (e < NE) atomicAdd(&g_cnt[ei[NE + e]], 1);
}

__global__ void __launch_bounds__(256) k_scan256() {
    __shared__ int ws[8], ws2[8], s_base;
    int b = blockIdx.x, t = threadIdx.x;
    int n = b * 256 + t;
    int lane = t & 31, w = t >> 5;
    int v = g_cnt[n] + 1;
    int x = v;
    #pragma unroll
    for (int o = 1; o < 32; o <<= 1) {
        int y = __shfl_up_sync(0xffffffffu, x, o);
        if (lane >= o) x += y;
    }
    if (lane == 31) ws[w] = x;
    __syncthreads();
    if (t < 8) {
        int s = ws[t];
        #pragma unroll
        for (int o = 1; o < 8; o <<= 1) {
            int y = __shfl_up_sync(0xffu, s, o);
            if (t >= o) s += y;
        }
        ws[t] = s;
    }
    __syncthreads();
    int intra = x - v + (w ? ws[w - 1] : 0);
    int total = ws[7];
    if (t == 0) atomicExch(&g_bsum[b], total);
    volatile int* vb = g_bsum;
    int av;
    while ((av = vb[t]) == 0) { }
    int contrib = (t < b) ? av : 0;
    #pragma unroll
    for (int o = 16; o; o >>= 1) contrib += __shfl_xor_sync(0xffffffffu, contrib, o);
    if (lane == 0) ws2[w] = contrib;
    __syncthreads();
    if (t == 0) {
        int s = 0;
        #pragma unroll
        for (int i = 0; i < 8; i++) s += ws2[i];
        s_base = s;
    }
    __syncthreads();
    int excl = s_base + intra;
    g_rowptr[n] = excl;
    g_wslot[n] = excl;
    if (n == NN - 1) g_rowptr[NN] = EX;
}

// warp handles 32 edges: coalesced 4KB attr load -> swizzled smem -> per-lane dots
__global__ void __launch_bounds__(256) k_scatter(const int* __restrict__ ei,
                                                 const float* __restrict__ ea) {
    __shared__ float sve[96];
    __shared__ __align__(16) char sbuf[8][4096];
    int tid = threadIdx.x;
    if (tid < 96) sve[tid] = ((const float*)g_ve)[tid];
    __syncthreads();
    int wid = tid >> 5, lane = tid & 31;
    int e = blockIdx.x * 256 + tid;
    int ebase = blockIdx.x * 256 + wid * 32;

    const float4* src = (const float4*)(ea + (size_t)ebase * 32);
    #pragma unroll
    for (int q = 0; q < 8; q++) {
        int idx = q * 32 + lane;
        uint32_t boff = (uint32_t)idx * 16u;
        uint32_t sw = boff ^ ((boff >> 3) & 0x70u);
        *(float4*)(sbuf[wid] + sw) = src[idx];
    }
    __syncwarp();

    float dot0 = 0.f, dot1 = 0.f, dot2 = 0.f;
    #pragma unroll
    for (int q = 0; q < 8; q++) {
        uint32_t boff = (uint32_t)lane * 128u + (uint32_t)q * 16u;
        uint32_t sw = boff ^ ((boff >> 3) & 0x70u);
        float4 v = *(const float4*)(sbuf[wid] + sw);
        const float* v0 = sve + 0 * 32 + q * 4;
        const float* v1 = sve + 1 * 32 + q * 4;
        const float* v2 = sve + 2 * 32 + q * 4;
        dot0 += v.x * v0[0] + v.y * v0[1] + v.z * v0[2] + v.w * v0[3];
        dot1 += v.x * v1[0] + v.y * v1[1] + v.z * v1[2] + v.w * v1[3];
        dot2 += v.x * v2[0] + v.y * v2[1] + v.z * v2[2] + v.w * v2[3];
    }

    int s = ei[e];
    int d = ei[NE + e];
    int p = atomicAdd(&g_wslot[d], 1);
    g_epk4[p] = make_int4(s, __float_as_int(dot0), __float_as_int(dot1), __float_as_int(dot2));
}

// ---------------- tensor-core GEMM + fused rowdots, fp16 h output (R6, proven) ----------------
__device__ __forceinline__ void mma16816(float* c, const unsigned* a, const unsigned* b) {
    asm volatile(
        "mma.sync.aligned.m16n8k16.row.col.f32.bf16.bf16.f32 "
        "{%0,%1,%2,%3},{%4,%5,%6,%7},{%8,%9},{%0,%1,%2,%3};\n"
        : "+f"(c[0]), "+f"(c[1]), "+f"(c[2]), "+f"(c[3])
        : "r"(a[0]), "r"(a[1]), "r"(a[2]), "r"(a[3]), "r"(b[0]), "r"(b[1]));
}

__device__ __forceinline__ void ldm_x4(unsigned* r, unsigned addr) {
    asm volatile("ldmatrix.sync.aligned.m8n8.x4.shared.b16 {%0,%1,%2,%3},[%4];"
                 : "=r"(r[0]), "=r"(r[1]), "=r"(r[2]), "=r"(r[3]) : "r"(addr));
}

__device__ __forceinline__ void ldm_x2(unsigned* r, unsigned addr) {
    asm volatile("ldmatrix.sync.aligned.m8n8.x2.shared.b16 {%0,%1},[%2];"
                 : "=r"(r[0]), "=r"(r[1]) : "r"(addr));
}

extern __shared__ char smem_raw[];

__global__ void __launch_bounds__(256) k_gemm_tc(const float* __restrict__ Ain, int l,
                                                 const float* __restrict__ a_s,
                                                 const float* __restrict__ a_d) {
    const float* A = Ain ? Ain : g_x;
    __nv_bfloat16* sAh = (__nv_bfloat16*)smem_raw;
    __nv_bfloat16* sAl = sAh + 128 * PK;
    __nv_bfloat16* sBh = sAl + 128 * PK;
    __nv_bfloat16* sBl = sBh + 128 * PK;

    int tid = threadIdx.x;
    int row0 = blockIdx.x * 128;

    {
        const float4* A4 = (const float4*)(A + (size_t)row0 * DD);
        #pragma unroll
        for (int it = 0; it < 16; it++) {
            int idx = it * 256 + tid;
            int r = idx >> 5;
            int c = (idx & 31) << 2;
            float4 v = A4[idx];
            __nv_bfloat16 h0 = __float2bfloat16_rn(v.x), h1 = __float2bfloat16_rn(v.y);
            __nv_bfloat16 h2 = __float2bfloat16_rn(v.z), h3 = __float2bfloat16_rn(v.w);
            __nv_bfloat162 ha, hb, la, lb;
            ha.x = h0; ha.y = h1; hb.x = h2; hb.y = h3;
            la = __floats2bfloat162_rn(v.x - __bfloat162float(h0), v.y - __bfloat162float(h1));
            lb = __floats2bfloat162_rn(v.z - __bfloat162float(h2), v.w - __bfloat162float(h3));
            unsigned* dh = (unsigned*)(sAh + r * PK + c);
            unsigned* dl = (unsigned*)(sAl + r * PK + c);
            dh[0] = *(unsigned*)&ha; dh[1] = *(unsigned*)&hb;
            dl[0] = *(unsigned*)&la; dl[1] = *(unsigned*)&lb;
        }
    }
    {
        const uint4* wh4 = (const uint4*)g_wh[l];
        const uint4* wl4 = (const uint4*)g_wl[l];
        #pragma unroll
        for (int it = 0; it < 8; it++) {
            int idx = it * 256 + tid;
            int n = idx >> 4;
            int kc = idx & 15;
            ((uint4*)(sBh + n * PK))[kc] = wh4[idx];
            ((uint4*)(sBl + n * PK))[kc] = wl4[idx];
        }
    }
    __syncthreads();

    int wid = tid >> 5, lane = tid & 31;
    int g = lane >> 2, tq = lane & 3;
    int wm = wid >> 2, wn = wid & 3;
    int mbase = wm * 64, nbase = wn * 32;

    unsigned baseAh, baseAl, baseBh, baseBl;
    {
        int aoff = ((mbase + (lane & 15)) * PK + ((lane >> 4) << 3)) * 2;
        baseAh = (unsigned)__cvta_generic_to_shared(sAh) + aoff;
        baseAl = (unsigned)__cvta_generic_to_shared(sAl) + aoff;
        int boff = ((nbase + (lane & 7)) * PK + (((lane >> 3) & 1) << 3)) * 2;
        baseBh = (unsigned)__cvta_generic_to_shared(sBh) + boff;
        baseBl = (unsigned)__cvta_generic_to_shared(sBl) + boff;
    }

    float acc[4][4][4];
    #pragma unroll
    for (int i = 0; i < 4; i++)
        #pragma unroll
        for (int j = 0; j < 4; j++)
            #pragma unroll
            for (int q = 0; q < 4; q++) acc[i][j][q] = 0.f;

    #pragma unroll
    for (int kk = 0; kk < 8; kk++) {
        unsigned kb = kk * 32;
        unsigned Ah[4][4], Al[4][4], Bh[4][2], Bl[4][2];
        #pragma unroll
        for (int i = 0; i < 4; i++) {
            unsigned off = (unsigned)(i * 16 * PK * 2) + kb;
            ldm_x4(Ah[i], baseAh + off);
            ldm_x4(Al[i], baseAl + off);
        }
        #pragma unroll
        for (int j = 0; j < 4; j++) {
            unsigned off = (unsigned)(j * 8 * PK * 2) + kb;
            ldm_x2(Bh[j], baseBh + off);
            ldm_x2(Bl[j], baseBl + off);
        }
        #pragma unroll
        for (int i = 0; i < 4; i++)
            #pragma unroll
            for (int j = 0; j < 4; j++) {
                mma16816(acc[i][j], Ah[i], Bh[j]);
                mma16816(acc[i][j], Al[i], Bh[j]);
                mma16816(acc[i][j], Ah[i], Bl[j]);
            }
    }

    // store h as fp16
    #pragma unroll
    for (int i = 0; i < 4; i++) {
        int r = row0 + mbase + i * 16 + g;
        #pragma unroll
        for (int j = 0; j < 4; j++) {
            int c = nbase + j * 8 + 2 * tq;
            *(__half2*)(g_hh + (size_t)r * DD + c) =
                __float22half2_rn(make_float2(acc[i][j][0], acc[i][j][1]));
            *(__half2*)(g_hh + (size_t)(r + 8) * DD + c) =
                __float22half2_rn(make_float2(acc[i][j][2], acc[i][j][3]));
        }
    }

    // fused rowdots
    float asv[4][2], adv[4][2];
    #pragma unroll
    for (int j = 0; j < 4; j++) {
        int c = nbase + j * 8 + 2 * tq;
        asv[j][0] = a_s[c]; asv[j][1] = a_s[c + 1];
        adv[j][0] = a_d[c]; adv[j][1] = a_d[c + 1];
    }
    __syncthreads();
    float* s_red = (float*)smem_raw;
    if (tid < 128) { s_red[tid] = 0.f; s_red[128 + tid] = 0.f; }
    __syncthreads();
    #pragma unroll
    for (int i = 0; i < 4; i++) {
        float ps0 = 0.f, pd0 = 0.f, ps1 = 0.f, pd1 = 0.f;
        #pragma unroll
        for (int j = 0; j < 4; j++) {
            ps0 += acc[i][j][0] * asv[j][0] + acc[i][j][1] * asv[j][1];
            pd0 += acc[i][j][0] * adv[j][0] + acc[i][j][1] * adv[j][1];
            ps1 += acc[i][j][2] * asv[j][0] + acc[i][j][3] * asv[j][1];
            pd1 += acc[i][j][2] * adv[j][0] + acc[i][j][3] * adv[j][1];
        }
        #pragma unroll
        for (int o = 1; o < 4; o <<= 1) {
            ps0 += __shfl_xor_sync(0xffffffffu, ps0, o);
            pd0 += __shfl_xor_sync(0xffffffffu, pd0, o);
            ps1 += __shfl_xor_sync(0xffffffffu, ps1, o);
            pd1 += __shfl_xor_sync(0xffffffffu, pd1, o);
        }
        if (tq == 0) {
            int rl = mbase + i * 16 + g;
            atomicAdd(&s_red[rl], ps0);
            atomicAdd(&s_red[128 + rl], pd0);
            atomicAdd(&s_red[rl + 8], ps1);
            atomicAdd(&s_red[128 + rl + 8], pd1);
        }
    }
    __syncthreads();
    if (tid < 128) {
        g_as[row0 + tid] = s_red[tid];
        g_ad[row0 + tid] = s_red[128 + tid];
    }
}

// ------- aggregate: 2 edges/warp via half-warps, inline self-loop, bias + GELU -------
__global__ void __launch_bounds__(256) k_agg(int l, const float* __restrict__ bias_l,
                                             float* __restrict__ outp) {
    int d = (blockIdx.x * blockDim.x + threadIdx.x) >> 5;
    int lane = threadIdx.x & 31;
    if (d >= NN) return;
    float* out = outp ? outp : g_x;

    int half = lane >> 4;            // 0: even edges, 1: odd edges
    int sl = lane & 15;              // 16B chunk index within the 256B fp16 row

    int beg = g_rowptr[d];
    int endE = g_rowptr[d + 1] - 1;
    float add = g_ad[d];
    float asd = g_as[d];
    const int4* ep = g_epk4;
    const uint4* h4 = (const uint4*)g_hh;   // 16 uint4 per row

    float den = 0.f;
    float ssum = 0.f;
    float acc[8];
    #pragma unroll
    for (int i = 0; i < 8; i++) acc[i] = 0.f;

    for (int base = beg; base < endE; base += 32) {
        int j = base + lane;
        float ex = 0.f;
        int s = 0;
        if (j < endE) {
            int4 e = ep[j];
            s = e.x;
            int sbi = (l == 0) ? e.y : (l == 1) ? e.z : e.w;
            float sc = __int_as_float(sbi);
            ssum += sc;
            float al = g_as[s] + add + sc;
            al = al > 0.f ? al : 0.2f * al;
            ex = __expf(al);
        }
        den += ex;

        int cnt = endE - base;
        if (cnt > 32) cnt = 32;
        for (int t = 0; t < cnt; t += 2) {
            int srcl = t + half;     // per-lane shfl source (out-of-range lanes carry ex=0)
            float ext = __shfl_sync(0xffffffffu, ex, srcl);
            int st = __shfl_sync(0xffffffffu, s, srcl);
            uint4 raw = h4[(size_t)st * 16 + sl];
            float2 v0 = __half22float2(*(__half2*)&raw.x);
            float2 v1 = __half22float2(*(__half2*)&raw.y);
            float2 v2 = __half22float2(*(__half2*)&raw.z);
            float2 v3 = __half22float2(*(__half2*)&raw.w);
            acc[0] = fmaf(ext, v0.x, acc[0]);
            acc[1] = fmaf(ext, v0.y, acc[1]);
            acc[2] = fmaf(ext, v1.x, acc[2]);
            acc[3] = fmaf(ext, v1.y, acc[3]);
            acc[4] = fmaf(ext, v2.x, acc[4]);
            acc[5] = fmaf(ext, v2.y, acc[5]);
            acc[6] = fmaf(ext, v3.x, acc[6]);
            acc[7] = fmaf(ext, v3.y, acc[7]);
        }
    }
    #pragma unroll
    for (int o = 16; o; o >>= 1) {
        den += __shfl_xor_sync(0xffffffffu, den, o);
        ssum += __shfl_xor_sync(0xffffffffu, ssum, o);
    }

    // combine halves: lane i += lane i+16
    #pragma unroll
    for (int i = 0; i < 8; i++)
        acc[i] += __shfl_down_sync(0xffffffffu, acc[i], 16);

    // self-loop
    float cf = fmaxf((float)(endE - beg), 1.0f);
    float als = asd + add + ssum / cf;
    als = als > 0.f ? als : 0.2f * als;
    float exs = __expf(als);
    den += exs;

    if (half == 0) {
        uint4 raw = h4[(size_t)d * 16 + sl];
        float2 v0 = __half22float2(*(__half2*)&raw.x);
        float2 v1 = __half22float2(*(__half2*)&raw.y);
        float2 v2 = __half22float2(*(__half2*)&raw.z);
        float2 v3 = __half22float2(*(__half2*)&raw.w);
        acc[0] = fmaf(exs, v0.x, acc[0]);
        acc[1] = fmaf(exs, v0.y, acc[1]);
        acc[2] = fmaf(exs, v1.x, acc[2]);
        acc[3] = fmaf(exs, v1.y, acc[3]);
        acc[4] = fmaf(exs, v2.x, acc[4]);
        acc[5] = fmaf(exs, v2.y, acc[5]);
        acc[6] = fmaf(exs, v3.x, acc[6]);
        acc[7] = fmaf(exs, v3.y, acc[7]);

        float r = 1.0f / den;
        const float* bb = bias_l + sl * 8;
        float4 o0, o1;
        o0.x = gelu_f(fmaf(acc[0], r, bb[0]));
        o0.y = gelu_f(fmaf(acc[1], r, bb[1]));
        o0.z = gelu_f(fmaf(acc[2], r, bb[2]));
        o0.w = gelu_f(fmaf(acc[3], r, bb[3]));
        o1.x = gelu_f(fmaf(acc[4], r, bb[4]));
        o1.y = gelu_f(fmaf(acc[5], r, bb[5]));
        o1.z = gelu_f(fmaf(acc[6], r, bb[6]));
        o1.w = gelu_f(fmaf(acc[7], r, bb[7]));
        float* orow = out + (size_t)d * DD + sl * 8;
        *(float4*)orow = o0;
        *(float4*)(orow + 4) = o1;
    }
}

// ---------------- launch ----------------
extern "C" void kernel_launch(void* const* d_in, const int* in_sizes, int n_in,
                              void* d_out, int out_size) {
    const float* x    = (const float*)d_in[0];
    const int*   ei   = (const int*)d_in[1];
    const float* ea   = (const float*)d_in[2];
    const float* Ws   = (const float*)d_in[3];
    const float* a_s  = (const float*)d_in[4];
    const float* a_d  = (const float*)d_in[5];
    const float* We   = (const float*)d_in[6];
    const float* ae   = (const float*)d_in[7];
    const float* bias = (const float*)d_in[8];
    float* out = (float*)d_out;

    const int SMEM_SZ = 4 * 128 * PK * 2;  // 139264 B
    cudaFuncSetAttribute(k_gemm_tc, cudaFuncAttributeMaxDynamicSharedMemorySize, SMEM_SZ);

    k_wsplit<<<449, 256>>>(Ws, We, ae);
    k_hist<<<NE / 256, 256>>>(ei);
    k_scan256<<<256, 256>>>();
    k_scatter<<<NE / 256, 256>>>(ei, ea);

    for (int l = 0; l < 3; l++) {
        const float* xin = (l == 0) ? x : nullptr;
        k_gemm_tc<<<NN / 128, 256, SMEM_SZ>>>(xin, l, a_s + l * DD, a_d + l * DD);
        float* outl = (l == 2) ? out : nullptr;
        k_agg<<<NN / 8, 256>>>(l, bias + l * DD, outl);
    }
}

// round 15
// speedup vs baseline: 1.1245x; 1.1245x over previous
#include <cuda_runtime.h>
#include <cuda_bf16.h>
#include <cuda_fp16.h>
#include <stdint.h>
#include <math.h>

#define NN 65536
#define NE 524288
#define EX (NE + NN)
#define DD 128
#define PK 136   // padded k-dim (bf16 elems); 272B rows => ldmatrix conflict-free

// ---------------- scratch (device globals: allocation-free) ----------------
__device__ __half g_hh[(size_t)NN * DD];           // 16MB: h in fp16 (agg gather path)
__device__ __nv_bfloat16 g_xh[(size_t)NN * DD];    // activations split hi
__device__ __nv_bfloat16 g_xl[(size_t)NN * DD];    // activations split lo
__device__ float g_as[NN];
__device__ float g_ad[NN];
__device__ int4  g_epk4[EX];                // packed (src, s0, s1, s2) per CSR slot
__device__ int   g_rowptr[NN + 1];
__device__ int   g_wslot[NN];
__device__ int   g_cnt[NN];
__device__ int   g_bsum[256];
__device__ float g_ve[3][32];
__device__ __nv_bfloat16 g_wh[3][DD * DD];   // W^T split hi (n-major)
__device__ __nv_bfloat16 g_wl[3][DD * DD];   // W^T split lo (n-major)

__device__ __forceinline__ float gelu_f(float x) {
    return 0.5f * x * (1.0f + erff(x * 0.7071067811865476f));
}

// ---------------- preprocessing ----------------
__global__ void k_wsplit(const float* __restrict__ Ws,
                         const float* __restrict__ We, const float* __restrict__ ae) {
    int b = blockIdx.x;
    if (b >= 193) {
        int i = (b - 193) * 256 + threadIdx.x;
        if (i < NN) g_cnt[i] = 0;
        if (i < 256) g_bsum[i] = 0;
        return;
    }
    if (b == 192) {
        int t = threadIdx.x;
        if (t < 96) {
            int l = t / 32, k = t % 32;
            const float* w = We + l * 32 * DD + k * DD;
            const float* a = ae + l * DD;
            float s = 0.f;
            #pragma unroll 8
            for (int d = 0; d < DD; d++) s += w[d] * a[d];
            g_ve[l][k] = s;
        }
        return;
    }
    int idx = b * blockDim.x + threadIdx.x;   // 3*128*128
    int l = idx >> 14;
    int rem = idx & 16383;
    int k = rem >> 7, n = rem & 127;
    float v = Ws[idx];
    __nv_bfloat16 h = __float2bfloat16_rn(v);
    float lo = v - __bfloat162float(h);
    g_wh[l][n * DD + k] = h;
    g_wl[l][n * DD + k] = __float2bfloat16_rn(lo);
}

__global__ void k_hist(const int* __restrict__ ei) {
    int e = blockIdx.x * blockDim.x + threadIdx.x;
    if (e < NE) atomicAdd(&g_cnt[ei[NE + e]], 1);
}

__global__ void __launch_bounds__(256) k_scan256() {
    __shared__ int ws[8], ws2[8], s_base;
    int b = blockIdx.x, t = threadIdx.x;
    int n = b * 256 + t;
    int lane = t & 31, w = t >> 5;
    int v = g_cnt[n] + 1;
    int x = v;
    #pragma unroll
    for (int o = 1; o < 32; o <<= 1) {
        int y = __shfl_up_sync(0xffffffffu, x, o);
        if (lane >= o) x += y;
    }
    if (lane == 31) ws[w] = x;
    __syncthreads();
    if (t < 8) {
        int s = ws[t];
        #pragma unroll
        for (int o = 1; o < 8; o <<= 1) {
            int y = __shfl_up_sync(0xffu, s, o);
            if (t >= o) s += y;
        }
        ws[t] = s;
    }
    __syncthreads();
    int intra = x - v + (w ? ws[w - 1] : 0);
    int total = ws[7];
    if (t == 0) atomicExch(&g_bsum[b], total);
    volatile int* vb = g_bsum;
    int av;
    while ((av = vb[t]) == 0) { }
    int contrib = (t < b) ? av : 0;
    #pragma unroll
    for (int o = 16; o; o >>= 1) contrib += __shfl_xor_sync(0xffffffffu, contrib, o);
    if (lane == 0) ws2[w] = contrib;
    __syncthreads();
    if (t == 0) {
        int s = 0;
        #pragma unroll
        for (int i = 0; i < 8; i++) s += ws2[i];
        s_base = s;
    }
    __syncthreads();
    int excl = s_base + intra;
    g_rowptr[n] = excl;
    g_wslot[n] = excl;
    if (n == NN - 1) g_rowptr[NN] = EX;
}

// warp handles 32 edges: coalesced 4KB attr load -> swizzled smem -> per-lane dots
__global__ void __launch_bounds__(256) k_scatter(const int* __restrict__ ei,
                                                 const float* __restrict__ ea) {
    __shared__ float sve[96];
    __shared__ __align__(16) char sbuf[8][4096];
    int tid = threadIdx.x;
    if (tid < 96) sve[tid] = ((const float*)g_ve)[tid];
    __syncthreads();
    int wid = tid >> 5, lane = tid & 31;
    int e = blockIdx.x * 256 + tid;
    int ebase = blockIdx.x * 256 + wid * 32;

    const float4* src = (const float4*)(ea + (size_t)ebase * 32);
    #pragma unroll
    for (int q = 0; q < 8; q++) {
        int idx = q * 32 + lane;
        uint32_t boff = (uint32_t)idx * 16u;
        uint32_t sw = boff ^ ((boff >> 3) & 0x70u);
        *(float4*)(sbuf[wid] + sw) = src[idx];
    }
    __syncwarp();

    float dot0 = 0.f, dot1 = 0.f, dot2 = 0.f;
    #pragma unroll
    for (int q = 0; q < 8; q++) {
        uint32_t boff = (uint32_t)lane * 128u + (uint32_t)q * 16u;
        uint32_t sw = boff ^ ((boff >> 3) & 0x70u);
        float4 v = *(const float4*)(sbuf[wid] + sw);
        const float* v0 = sve + 0 * 32 + q * 4;
        const float* v1 = sve + 1 * 32 + q * 4;
        const float* v2 = sve + 2 * 32 + q * 4;
        dot0 += v.x * v0[0] + v.y * v0[1] + v.z * v0[2] + v.w * v0[3];
        dot1 += v.x * v1[0] + v.y * v1[1] + v.z * v1[2] + v.w * v1[3];
        dot2 += v.x * v2[0] + v.y * v2[1] + v.z * v2[2] + v.w * v2[3];
    }

    int s = ei[e];
    int d = ei[NE + e];
    int p = atomicAdd(&g_wslot[d], 1);
    g_epk4[p] = make_int4(s, __float_as_int(dot0), __float_as_int(dot1), __float_as_int(dot2));
}

// ---------------- tensor-core GEMM + fused rowdots, fp16 h output ----------------
__device__ __forceinline__ void mma16816(float* c, const unsigned* a, const unsigned* b) {
    asm volatile(
        "mma.sync.aligned.m16n8k16.row.col.f32.bf16.bf16.f32 "
        "{%0,%1,%2,%3},{%4,%5,%6,%7},{%8,%9},{%0,%1,%2,%3};\n"
        : "+f"(c[0]), "+f"(c[1]), "+f"(c[2]), "+f"(c[3])
        : "r"(a[0]), "r"(a[1]), "r"(a[2]), "r"(a[3]), "r"(b[0]), "r"(b[1]));
}

__device__ __forceinline__ void ldm_x4(unsigned* r, unsigned addr) {
    asm volatile("ldmatrix.sync.aligned.m8n8.x4.shared.b16 {%0,%1,%2,%3},[%4];"
                 : "=r"(r[0]), "=r"(r[1]), "=r"(r[2]), "=r"(r[3]) : "r"(addr));
}

__device__ __forceinline__ void ldm_x2(unsigned* r, unsigned addr) {
    asm volatile("ldmatrix.sync.aligned.m8n8.x2.shared.b16 {%0,%1},[%2];"
                 : "=r"(r[0]), "=r"(r[1]) : "r"(addr));
}

extern __shared__ char smem_raw[];

__global__ void __launch_bounds__(256) k_gemm_tc(const float* __restrict__ Ain, int l,
                                                 const float* __restrict__ a_s,
                                                 const float* __restrict__ a_d) {
    __nv_bfloat16* sAh = (__nv_bfloat16*)smem_raw;
    __nv_bfloat16* sAl = sAh + 128 * PK;
    __nv_bfloat16* sBh = sAl + 128 * PK;
    __nv_bfloat16* sBl = sBh + 128 * PK;

    int tid = threadIdx.x;
    int row0 = blockIdx.x * 128;

    if (Ain) {
        // layer 0: fp32 input, split on the fly
        const float4* A4 = (const float4*)(Ain + (size_t)row0 * DD);
        #pragma unroll
        for (int it = 0; it < 16; it++) {
            int idx = it * 256 + tid;
            int r = idx >> 5;
            int c = (idx & 31) << 2;
            float4 v = A4[idx];
            __nv_bfloat16 h0 = __float2bfloat16_rn(v.x), h1 = __float2bfloat16_rn(v.y);
            __nv_bfloat16 h2 = __float2bfloat16_rn(v.z), h3 = __float2bfloat16_rn(v.w);
            __nv_bfloat162 ha, hb, la, lb;
            ha.x = h0; ha.y = h1; hb.x = h2; hb.y = h3;
            la = __floats2bfloat162_rn(v.x - __bfloat162float(h0), v.y - __bfloat162float(h1));
            lb = __floats2bfloat162_rn(v.z - __bfloat162float(h2), v.w - __bfloat162float(h3));
            unsigned* dh = (unsigned*)(sAh + r * PK + c);
            unsigned* dl = (unsigned*)(sAl + r * PK + c);
            dh[0] = *(unsigned*)&ha; dh[1] = *(unsigned*)&hb;
            dl[0] = *(unsigned*)&la; dl[1] = *(unsigned*)&lb;
        }
    } else {
        // layers 1,2: pre-split activations, pure uint4 copy
        const uint4* axh = (const uint4*)(g_xh + (size_t)row0 * DD);
        const uint4* axl = (const uint4*)(g_xl + (size_t)row0 * DD);
        #pragma unroll
        for (int it = 0; it < 8; it++) {
            int idx = it * 256 + tid;
            int r = idx >> 4;
            int kc = idx & 15;
            ((uint4*)(sAh + r * PK))[kc] = axh[idx];
            ((uint4*)(sAl + r * PK))[kc] = axl[idx];
        }
    }
    {
        const uint4* wh4 = (const uint4*)g_wh[l];
        const uint4* wl4 = (const uint4*)g_wl[l];
        #pragma unroll
        for (int it = 0; it < 8; it++) {
            int idx = it * 256 + tid;
            int n = idx >> 4;
            int kc = idx & 15;
            ((uint4*)(sBh + n * PK))[kc] = wh4[idx];
            ((uint4*)(sBl + n * PK))[kc] = wl4[idx];
        }
    }
    __syncthreads();

    int wid = tid >> 5, lane = tid & 31;
    int g = lane >> 2, tq = lane & 3;
    int wm = wid >> 2, wn = wid & 3;
    int mbase = wm * 64, nbase = wn * 32;

    unsigned baseAh, baseAl, baseBh, baseBl;
    {
        int aoff = ((mbase + (lane & 15)) * PK + ((lane >> 4) << 3)) * 2;
        baseAh = (unsigned)__cvta_generic_to_shared(sAh) + aoff;
        baseAl = (unsigned)__cvta_generic_to_shared(sAl) + aoff;
        int boff = ((nbase + (lane & 7)) * PK + (((lane >> 3) & 1) << 3)) * 2;
        baseBh = (unsigned)__cvta_generic_to_shared(sBh) + boff;
        baseBl = (unsigned)__cvta_generic_to_shared(sBl) + boff;
    }

    float acc[4][4][4];
    #pragma unroll
    for (int i = 0; i < 4; i++)
        #pragma unroll
        for (int j = 0; j < 4; j++)
            #pragma unroll
            for (int q = 0; q < 4; q++) acc[i][j][q] = 0.f;

    #pragma unroll
    for (int kk = 0; kk < 8; kk++) {
        unsigned kb = kk * 32;
        unsigned Ah[4][4], Al[4][4], Bh[4][2], Bl[4][2];
        #pragma unroll
        for (int i = 0; i < 4; i++) {
            unsigned off = (unsigned)(i * 16 * PK * 2) + kb;
            ldm_x4(Ah[i], baseAh + off);
            ldm_x4(Al[i], baseAl + off);
        }
        #pragma unroll
        for (int j = 0; j < 4; j++) {
            unsigned off = (unsigned)(j * 8 * PK * 2) + kb;
            ldm_x2(Bh[j], baseBh + off);
            ldm_x2(Bl[j], baseBl + off);
        }
        #pragma unroll
        for (int i = 0; i < 4; i++)
            #pragma unroll
            for (int j = 0; j < 4; j++) {
                mma16816(acc[i][j], Ah[i], Bh[j]);
                mma16816(acc[i][j], Al[i], Bh[j]);
                mma16816(acc[i][j], Ah[i], Bl[j]);
            }
    }

    // store h as fp16
    #pragma unroll
    for (int i = 0; i < 4; i++) {
        int r = row0 + mbase + i * 16 + g;
        #pragma unroll
        for (int j = 0; j < 4; j++) {
            int c = nbase + j * 8 + 2 * tq;
            *(__half2*)(g_hh + (size_t)r * DD + c) =
                __float22half2_rn(make_float2(acc[i][j][0], acc[i][j][1]));
            *(__half2*)(g_hh + (size_t)(r + 8) * DD + c) =
                __float22half2_rn(make_float2(acc[i][j][2], acc[i][j][3]));
        }
    }

    // fused rowdots
    float asv[4][2], adv[4][2];
    #pragma unroll
    for (int j = 0; j < 4; j++) {
        int c = nbase + j * 8 + 2 * tq;
        asv[j][0] = a_s[c]; asv[j][1] = a_s[c + 1];
        adv[j][0] = a_d[c]; adv[j][1] = a_d[c + 1];
    }
    __syncthreads();
    float* s_red = (float*)smem_raw;
    if (tid < 128) { s_red[tid] = 0.f; s_red[128 + tid] = 0.f; }
    __syncthreads();
    #pragma unroll
    for (int i = 0; i < 4; i++) {
        float ps0 = 0.f, pd0 = 0.f, ps1 = 0.f, pd1 = 0.f;
        #pragma unroll
        for (int j = 0; j < 4; j++) {
            ps0 += acc[i][j][0] * asv[j][0] + acc[i][j][1] * asv[j][1];
            pd0 += acc[i][j][0] * adv[j][0] + acc[i][j][1] * adv[j][1];
            ps1 += acc[i][j][2] * asv[j][0] + acc[i][j][3] * asv[j][1];
            pd1 += acc[i][j][2] * adv[j][0] + acc[i][j][3] * adv[j][1];
        }
        #pragma unroll
        for (int o = 1; o < 4; o <<= 1) {
            ps0 += __shfl_xor_sync(0xffffffffu, ps0, o);
            pd0 += __shfl_xor_sync(0xffffffffu, pd0, o);
            ps1 += __shfl_xor_sync(0xffffffffu, ps1, o);
            pd1 += __shfl_xor_sync(0xffffffffu, pd1, o);
        }
        if (tq == 0) {
            int rl = mbase + i * 16 + g;
            atomicAdd(&s_red[rl], ps0);
            atomicAdd(&s_red[128 + rl], pd0);
            atomicAdd(&s_red[rl + 8], ps1);
            atomicAdd(&s_red[128 + rl + 8], pd1);
        }
    }
    __syncthreads();
    if (tid < 128) {
        g_as[row0 + tid] = s_red[tid];
        g_ad[row0 + tid] = s_red[128 + tid];
    }
}

// ------- aggregate (R13 form, 4-way unroll) + inline self-loop + bias + GELU -------
__global__ void __launch_bounds__(256) k_agg(int l, const float* __restrict__ bias_l,
                                             float* __restrict__ outp) {
    int d = (blockIdx.x * blockDim.x + threadIdx.x) >> 5;
    int lane = threadIdx.x & 31;
    if (d >= NN) return;

    int beg = g_rowptr[d];
    int endE = g_rowptr[d + 1] - 1;   // real edges in [beg, endE); self-loop at endE
    float add = g_ad[d];
    float asd = g_as[d];
    const int4* ep = g_epk4;
    const uint2* h2 = (const uint2*)g_hh;

    float den = 0.f;
    float ssum = 0.f;
    float4 acc = make_float4(0.f, 0.f, 0.f, 0.f);

    for (int base = beg; base < endE; base += 32) {
        int j = base + lane;
        float ex = 0.f;
        int s = 0;
        if (j < endE) {
            int4 e = ep[j];
            s = e.x;
            int sbi = (l == 0) ? e.y : (l == 1) ? e.z : e.w;
            float sc = __int_as_float(sbi);
            ssum += sc;
            float al = g_as[s] + add + sc;
            al = al > 0.f ? al : 0.2f * al;
            ex = __expf(al);
        }
        den += ex;

        int cnt = endE - base;
        if (cnt > 32) cnt = 32;
        int t = 0;
        for (; t + 4 <= cnt; t += 4) {
            float e0 = __shfl_sync(0xffffffffu, ex, t);
            float e1 = __shfl_sync(0xffffffffu, ex, t + 1);
            float e2 = __shfl_sync(0xffffffffu, ex, t + 2);
            float e3 = __shfl_sync(0xffffffffu, ex, t + 3);
            int s0 = __shfl_sync(0xffffffffu, s, t);
            int s1 = __shfl_sync(0xffffffffu, s, t + 1);
            int s2 = __shfl_sync(0xffffffffu, s, t + 2);
            int s3 = __shfl_sync(0xffffffffu, s, t + 3);
            uint2 r0 = h2[(size_t)s0 * 32 + lane];
            uint2 r1 = h2[(size_t)s1 * 32 + lane];
            uint2 r2 = h2[(size_t)s2 * 32 + lane];
            uint2 r3 = h2[(size_t)s3 * 32 + lane];
            float2 a0 = __half22float2(*(__half2*)&r0.x), b0 = __half22float2(*(__half2*)&r0.y);
            float2 a1 = __half22float2(*(__half2*)&r1.x), b1 = __half22float2(*(__half2*)&r1.y);
            float2 a2 = __half22float2(*(__half2*)&r2.x), b2 = __half22float2(*(__half2*)&r2.y);
            float2 a3 = __half22float2(*(__half2*)&r3.x), b3 = __half22float2(*(__half2*)&r3.y);
            acc.x = fmaf(e0, a0.x, fmaf(e1, a1.x, fmaf(e2, a2.x, fmaf(e3, a3.x, acc.x))));
            acc.y = fmaf(e0, a0.y, fmaf(e1, a1.y, fmaf(e2, a2.y, fmaf(e3, a3.y, acc.y))));
            acc.z = fmaf(e0, b0.x, fmaf(e1, b1.x, fmaf(e2, b2.x, fmaf(e3, b3.x, acc.z))));
            acc.w = fmaf(e0, b0.y, fmaf(e1, b1.y, fmaf(e2, b2.y, fmaf(e3, b3.y, acc.w))));
        }
        for (; t < cnt; t++) {
            float e0 = __shfl_sync(0xffffffffu, ex, t);
            int s0 = __shfl_sync(0xffffffffu, s, t);
            uint2 r0 = h2[(size_t)s0 * 32 + lane];
            float2 a0 = __half22float2(*(__half2*)&r0.x);
            float2 b0 = __half22float2(*(__half2*)&r0.y);
            acc.x = fmaf(e0, a0.x, acc.x);
            acc.y = fmaf(e0, a0.y, acc.y);
            acc.z = fmaf(e0, b0.x, acc.z);
            acc.w = fmaf(e0, b0.y, acc.w);
        }
    }
    #pragma unroll
    for (int o = 16; o; o >>= 1) {
        den += __shfl_xor_sync(0xffffffffu, den, o);
        ssum += __shfl_xor_sync(0xffffffffu, ssum, o);
    }

    // self-loop: score = mean of incoming scores (0 if none)
    float cf = fmaxf((float)(endE - beg), 1.0f);
    float als = asd + add + ssum / cf;
    als = als > 0.f ? als : 0.2f * als;
    float exs = __expf(als);
    den += exs;
    {
        uint2 raw = h2[(size_t)d * 32 + lane];
        float2 v0 = __half22float2(*(__half2*)&raw.x);
        float2 v1 = __half22float2(*(__half2*)&raw.y);
        acc.x = fmaf(exs, v0.x, acc.x);
        acc.y = fmaf(exs, v0.y, acc.y);
        acc.z = fmaf(exs, v1.x, acc.z);
        acc.w = fmaf(exs, v1.y, acc.w);
    }

    float r = 1.0f / den;
    float4 b4 = ((const float4*)bias_l)[lane];
    float4 o4;
    o4.x = gelu_f(fmaf(acc.x, r, b4.x));
    o4.y = gelu_f(fmaf(acc.y, r, b4.y));
    o4.z = gelu_f(fmaf(acc.z, r, b4.z));
    o4.w = gelu_f(fmaf(acc.w, r, b4.w));

    if (outp) {
        ((float4*)outp)[(size_t)d * 32 + lane] = o4;
    } else {
        // pre-split for next GEMM: bf16 hi + lo, 8B each, coalesced
        __nv_bfloat16 h0 = __float2bfloat16_rn(o4.x), h1 = __float2bfloat16_rn(o4.y);
        __nv_bfloat16 h2b = __float2bfloat16_rn(o4.z), h3 = __float2bfloat16_rn(o4.w);
        __nv_bfloat162 ha, hb;
        ha.x = h0; ha.y = h1; hb.x = h2b; hb.y = h3;
        __nv_bfloat162 la = __floats2bfloat162_rn(o4.x - __bfloat162float(h0),
                                                  o4.y - __bfloat162float(h1));
        __nv_bfloat162 lb = __floats2bfloat162_rn(o4.z - __bfloat162float(h2b),
                                                  o4.w - __bfloat162float(h3));
        uint2 ph, pl;
        ph.x = *(unsigned*)&ha; ph.y = *(unsigned*)&hb;
        pl.x = *(unsigned*)&la; pl.y = *(unsigned*)&lb;
        ((uint2*)g_xh)[(size_t)d * 32 + lane] = ph;
        ((uint2*)g_xl)[(size_t)d * 32 + lane] = pl;
    }
}

// ---------------- launch ----------------
extern "C" void kernel_launch(void* const* d_in, const int* in_sizes, int n_in,
                              void* d_out, int out_size) {
    const float* x    = (const float*)d_in[0];
    const int*   ei   = (const int*)d_in[1];
    const float* ea   = (const float*)d_in[2];
    const float* Ws   = (const float*)d_in[3];
    const float* a_s  = (const float*)d_in[4];
    const float* a_d  = (const float*)d_in[5];
    const float* We   = (const float*)d_in[6];
    const float* ae   = (const float*)d_in[7];
    const float* bias = (const float*)d_in[8];
    float* out = (float*)d_out;

    const int SMEM_SZ = 4 * 128 * PK * 2;  // 139264 B
    cudaFuncSetAttribute(k_gemm_tc, cudaFuncAttributeMaxDynamicSharedMemorySize, SMEM_SZ);

    k_wsplit<<<449, 256>>>(Ws, We, ae);
    k_hist<<<NE / 256, 256>>>(ei);
    k_scan256<<<256, 256>>>();
    k_scatter<<<NE / 256, 256>>>(ei, ea);

    for (int l = 0; l < 3; l++) {
        const float* xin = (l == 0) ? x : nullptr;     // nullptr -> pre-split g_xh/g_xl
        k_gemm_tc<<<NN / 128, 256, SMEM_SZ>>>(xin, l, a_s + l * DD, a_d + l * DD);
        float* outl = (l == 2) ? out : nullptr;        // nullptr -> split store to g_xh/g_xl
        k_agg<<<NN / 8, 256>>>(l, bias + l * DD, outl);
    }
}

// round 16
// speedup vs baseline: 1.1590x; 1.0308x over previous
#include <cuda_runtime.h>
#include <cuda_bf16.h>
#include <cuda_fp16.h>
#include <stdint.h>
#include <math.h>

#define NN 65536
#define NE 524288
#define EX (NE + NN)
#define DD 128
#define PK 136   // padded k-dim (bf16 elems); 272B rows => ldmatrix conflict-free

// ---------------- scratch (device globals: allocation-free) ----------------
__device__ __half g_hh[(size_t)NN * DD];           // 16MB: h in fp16 (agg gather path)
__device__ __nv_bfloat16 g_xh[(size_t)NN * DD];    // activations split hi
__device__ __nv_bfloat16 g_xl[(size_t)NN * DD];    // activations split lo
__device__ float g_as[NN];
__device__ float g_ad[NN];
__device__ int4  g_epk4[EX];                // packed (src, s0, s1, s2) per CSR slot
__device__ int   g_rowptr[NN + 1];
__device__ int   g_wslot[NN];
__device__ int   g_cnt[NN];
__device__ int   g_bsum[256];
__device__ float g_ve[3][32];
__device__ __nv_bfloat16 g_wh[3][DD * DD];   // W^T split hi (n-major)
__device__ __nv_bfloat16 g_wl[3][DD * DD];   // W^T split lo (n-major)

__device__ __forceinline__ float gelu_f(float x) {
    return 0.5f * x * (1.0f + erff(x * 0.7071067811865476f));
}

// ---------------- preprocessing ----------------
__global__ void k_wsplit(const float* __restrict__ Ws,
                         const float* __restrict__ We, const float* __restrict__ ae) {
    int b = blockIdx.x;
    if (b >= 193) {
        int i = (b - 193) * 256 + threadIdx.x;
        if (i < NN) g_cnt[i] = 0;
        if (i < 256) g_bsum[i] = 0;
        return;
    }
    if (b == 192) {
        int t = threadIdx.x;
        if (t < 96) {
            int l = t / 32, k = t % 32;
            const float* w = We + l * 32 * DD + k * DD;
            const float* a = ae + l * DD;
            float s = 0.f;
            #pragma unroll 8
            for (int d = 0; d < DD; d++) s += w[d] * a[d];
            g_ve[l][k] = s;
        }
        return;
    }
    int idx = b * blockDim.x + threadIdx.x;   // 3*128*128
    int l = idx >> 14;
    int rem = idx & 16383;
    int k = rem >> 7, n = rem & 127;
    float v = Ws[idx];
    __nv_bfloat16 h = __float2bfloat16_rn(v);
    float lo = v - __bfloat162float(h);
    g_wh[l][n * DD + k] = h;
    g_wl[l][n * DD + k] = __float2bfloat16_rn(lo);
}

__global__ void k_hist(const int* __restrict__ ei) {
    int e = blockIdx.x * blockDim.x + threadIdx.x;
    if (e < NE) atomicAdd(&g_cnt[ei[NE + e]], 1);
}

__global__ void __launch_bounds__(256) k_scan256() {
    __shared__ int ws[8], ws2[8], s_base;
    int b = blockIdx.x, t = threadIdx.x;
    int n = b * 256 + t;
    int lane = t & 31, w = t >> 5;
    int v = g_cnt[n] + 1;
    int x = v;
    #pragma unroll
    for (int o = 1; o < 32; o <<= 1) {
        int y = __shfl_up_sync(0xffffffffu, x, o);
        if (lane >= o) x += y;
    }
    if (lane == 31) ws[w] = x;
    __syncthreads();
    if (t < 8) {
        int s = ws[t];
        #pragma unroll
        for (int o = 1; o < 8; o <<= 1) {
            int y = __shfl_up_sync(0xffu, s, o);
            if (t >= o) s += y;
        }
        ws[t] = s;
    }
    __syncthreads();
    int intra = x - v + (w ? ws[w - 1] : 0);
    int total = ws[7];
    if (t == 0) atomicExch(&g_bsum[b], total);
    volatile int* vb = g_bsum;
    int av;
    while ((av = vb[t]) == 0) { }
    int contrib = (t < b) ? av : 0;
    #pragma unroll
    for (int o = 16; o; o >>= 1) contrib += __shfl_xor_sync(0xffffffffu, contrib, o);
    if (lane == 0) ws2[w] = contrib;
    __syncthreads();
    if (t == 0) {
        int s = 0;
        #pragma unroll
        for (int i = 0; i < 8; i++) s += ws2[i];
        s_base = s;
    }
    __syncthreads();
    int excl = s_base + intra;
    g_rowptr[n] = excl;
    g_wslot[n] = excl;
    if (n == NN - 1) g_rowptr[NN] = EX;
}

// warp handles 32 edges: coalesced 4KB attr load -> swizzled smem -> per-lane dots
__global__ void __launch_bounds__(256) k_scatter(const int* __restrict__ ei,
                                                 const float* __restrict__ ea) {
    __shared__ float sve[96];
    __shared__ __align__(16) char sbuf[8][4096];
    int tid = threadIdx.x;
    if (tid < 96) sve[tid] = ((const float*)g_ve)[tid];
    __syncthreads();
    int wid = tid >> 5, lane = tid & 31;
    int e = blockIdx.x * 256 + tid;
    int ebase = blockIdx.x * 256 + wid * 32;

    const float4* src = (const float4*)(ea + (size_t)ebase * 32);
    #pragma unroll
    for (int q = 0; q < 8; q++) {
        int idx = q * 32 + lane;
        uint32_t boff = (uint32_t)idx * 16u;
        uint32_t sw = boff ^ ((boff >> 3) & 0x70u);
        *(float4*)(sbuf[wid] + sw) = src[idx];
    }
    __syncwarp();

    float dot0 = 0.f, dot1 = 0.f, dot2 = 0.f;
    #pragma unroll
    for (int q = 0; q < 8; q++) {
        uint32_t boff = (uint32_t)lane * 128u + (uint32_t)q * 16u;
        uint32_t sw = boff ^ ((boff >> 3) & 0x70u);
        float4 v = *(const float4*)(sbuf[wid] + sw);
        const float* v0 = sve + 0 * 32 + q * 4;
        const float* v1 = sve + 1 * 32 + q * 4;
        const float* v2 = sve + 2 * 32 + q * 4;
        dot0 += v.x * v0[0] + v.y * v0[1] + v.z * v0[2] + v.w * v0[3];
        dot1 += v.x * v1[0] + v.y * v1[1] + v.z * v1[2] + v.w * v1[3];
        dot2 += v.x * v2[0] + v.y * v2[1] + v.z * v2[2] + v.w * v2[3];
    }

    int s = ei[e];
    int d = ei[NE + e];
    int p = atomicAdd(&g_wslot[d], 1);
    g_epk4[p] = make_int4(s, __float_as_int(dot0), __float_as_int(dot1), __float_as_int(dot2));
}

// ---------------- tensor-core GEMM + fused rowdots, fp16 h output ----------------
__device__ __forceinline__ void mma16816(float* c, const unsigned* a, const unsigned* b) {
    asm volatile(
        "mma.sync.aligned.m16n8k16.row.col.f32.bf16.bf16.f32 "
        "{%0,%1,%2,%3},{%4,%5,%6,%7},{%8,%9},{%0,%1,%2,%3};\n"
        : "+f"(c[0]), "+f"(c[1]), "+f"(c[2]), "+f"(c[3])
        : "r"(a[0]), "r"(a[1]), "r"(a[2]), "r"(a[3]), "r"(b[0]), "r"(b[1]));
}

__device__ __forceinline__ void ldm_x4(unsigned* r, unsigned addr) {
    asm volatile("ldmatrix.sync.aligned.m8n8.x4.shared.b16 {%0,%1,%2,%3},[%4];"
                 : "=r"(r[0]), "=r"(r[1]), "=r"(r[2]), "=r"(r[3]) : "r"(addr));
}

__device__ __forceinline__ void ldm_x2(unsigned* r, unsigned addr) {
    asm volatile("ldmatrix.sync.aligned.m8n8.x2.shared.b16 {%0,%1},[%2];"
                 : "=r"(r[0]), "=r"(r[1]) : "r"(addr));
}

extern __shared__ char smem_raw[];

__global__ void __launch_bounds__(256) k_gemm_tc(const float* __restrict__ Ain, int l,
                                                 const float* __restrict__ a_s,
                                                 const float* __restrict__ a_d) {
    __nv_bfloat16* sAh = (__nv_bfloat16*)smem_raw;
    __nv_bfloat16* sAl = sAh + 128 * PK;
    __nv_bfloat16* sBh = sAl + 128 * PK;
    __nv_bfloat16* sBl = sBh + 128 * PK;

    int tid = threadIdx.x;
    int row0 = blockIdx.x * 128;

    if (Ain) {
        const float4* A4 = (const float4*)(Ain + (size_t)row0 * DD);
        #pragma unroll
        for (int it = 0; it < 16; it++) {
            int idx = it * 256 + tid;
            int r = idx >> 5;
            int c = (idx & 31) << 2;
            float4 v = A4[idx];
            __nv_bfloat16 h0 = __float2bfloat16_rn(v.x), h1 = __float2bfloat16_rn(v.y);
            __nv_bfloat16 h2 = __float2bfloat16_rn(v.z), h3 = __float2bfloat16_rn(v.w);
            __nv_bfloat162 ha, hb, la, lb;
            ha.x = h0; ha.y = h1; hb.x = h2; hb.y = h3;
            la = __floats2bfloat162_rn(v.x - __bfloat162float(h0), v.y - __bfloat162float(h1));
            lb = __floats2bfloat162_rn(v.z - __bfloat162float(h2), v.w - __bfloat162float(h3));
            unsigned* dh = (unsigned*)(sAh + r * PK + c);
            unsigned* dl = (unsigned*)(sAl + r * PK + c);
            dh[0] = *(unsigned*)&ha; dh[1] = *(unsigned*)&hb;
            dl[0] = *(unsigned*)&la; dl[1] = *(unsigned*)&lb;
        }
    } else {
        const uint4* axh = (const uint4*)(g_xh + (size_t)row0 * DD);
        const uint4* axl = (const uint4*)(g_xl + (size_t)row0 * DD);
        #pragma unroll
        for (int it = 0; it < 8; it++) {
            int idx = it * 256 + tid;
            int r = idx >> 4;
            int kc = idx & 15;
            ((uint4*)(sAh + r * PK))[kc] = axh[idx];
            ((uint4*)(sAl + r * PK))[kc] = axl[idx];
        }
    }
    {
        const uint4* wh4 = (const uint4*)g_wh[l];
        const uint4* wl4 = (const uint4*)g_wl[l];
        #pragma unroll
        for (int it = 0; it < 8; it++) {
            int idx = it * 256 + tid;
            int n = idx >> 4;
            int kc = idx & 15;
            ((uint4*)(sBh + n * PK))[kc] = wh4[idx];
            ((uint4*)(sBl + n * PK))[kc] = wl4[idx];
        }
    }
    __syncthreads();

    int wid = tid >> 5, lane = tid & 31;
    int g = lane >> 2, tq = lane & 3;
    int wm = wid >> 2, wn = wid & 3;
    int mbase = wm * 64, nbase = wn * 32;

    unsigned baseAh, baseAl, baseBh, baseBl;
    {
        int aoff = ((mbase + (lane & 15)) * PK + ((lane >> 4) << 3)) * 2;
        baseAh = (unsigned)__cvta_generic_to_shared(sAh) + aoff;
        baseAl = (unsigned)__cvta_generic_to_shared(sAl) + aoff;
        int boff = ((nbase + (lane & 7)) * PK + (((lane >> 3) & 1) << 3)) * 2;
        baseBh = (unsigned)__cvta_generic_to_shared(sBh) + boff;
        baseBl = (unsigned)__cvta_generic_to_shared(sBl) + boff;
    }

    float acc[4][4][4];
    #pragma unroll
    for (int i = 0; i < 4; i++)
        #pragma unroll
        for (int j = 0; j < 4; j++)
            #pragma unroll
            for (int q = 0; q < 4; q++) acc[i][j][q] = 0.f;

    #pragma unroll
    for (int kk = 0; kk < 8; kk++) {
        unsigned kb = kk * 32;
        unsigned Ah[4][4], Al[4][4], Bh[4][2], Bl[4][2];
        #pragma unroll
        for (int i = 0; i < 4; i++) {
            unsigned off = (unsigned)(i * 16 * PK * 2) + kb;
            ldm_x4(Ah[i], baseAh + off);
            ldm_x4(Al[i], baseAl + off);
        }
        #pragma unroll
        for (int j = 0; j < 4; j++) {
            unsigned off = (unsigned)(j * 8 * PK * 2) + kb;
            ldm_x2(Bh[j], baseBh + off);
            ldm_x2(Bl[j], baseBl + off);
        }
        #pragma unroll
        for (int i = 0; i < 4; i++)
            #pragma unroll
            for (int j = 0; j < 4; j++) {
                mma16816(acc[i][j], Ah[i], Bh[j]);
                mma16816(acc[i][j], Al[i], Bh[j]);
                mma16816(acc[i][j], Ah[i], Bl[j]);
            }
    }

    // store h as fp16
    #pragma unroll
    for (int i = 0; i < 4; i++) {
        int r = row0 + mbase + i * 16 + g;
        #pragma unroll
        for (int j = 0; j < 4; j++) {
            int c = nbase + j * 8 + 2 * tq;
            *(__half2*)(g_hh + (size_t)r * DD + c) =
                __float22half2_rn(make_float2(acc[i][j][0], acc[i][j][1]));
            *(__half2*)(g_hh + (size_t)(r + 8) * DD + c) =
                __float22half2_rn(make_float2(acc[i][j][2], acc[i][j][3]));
        }
    }

    // fused rowdots
    float asv[4][2], adv[4][2];
    #pragma unroll
    for (int j = 0; j < 4; j++) {
        int c = nbase + j * 8 + 2 * tq;
        asv[j][0] = a_s[c]; asv[j][1] = a_s[c + 1];
        adv[j][0] = a_d[c]; adv[j][1] = a_d[c + 1];
    }
    __syncthreads();
    float* s_red = (float*)smem_raw;
    if (tid < 128) { s_red[tid] = 0.f; s_red[128 + tid] = 0.f; }
    __syncthreads();
    #pragma unroll
    for (int i = 0; i < 4; i++) {
        float ps0 = 0.f, pd0 = 0.f, ps1 = 0.f, pd1 = 0.f;
        #pragma unroll
        for (int j = 0; j < 4; j++) {
            ps0 += acc[i][j][0] * asv[j][0] + acc[i][j][1] * asv[j][1];
            pd0 += acc[i][j][0] * adv[j][0] + acc[i][j][1] * adv[j][1];
            ps1 += acc[i][j][2] * asv[j][0] + acc[i][j][3] * asv[j][1];
            pd1 += acc[i][j][2] * adv[j][0] + acc[i][j][3] * adv[j][1];
        }
        #pragma unroll
        for (int o = 1; o < 4; o <<= 1) {
            ps0 += __shfl_xor_sync(0xffffffffu, ps0, o);
            pd0 += __shfl_xor_sync(0xffffffffu, pd0, o);
            ps1 += __shfl_xor_sync(0xffffffffu, ps1, o);
            pd1 += __shfl_xor_sync(0xffffffffu, pd1, o);
        }
        if (tq == 0) {
            int rl = mbase + i * 16 + g;
            atomicAdd(&s_red[rl], ps0);
            atomicAdd(&s_red[128 + rl], pd0);
            atomicAdd(&s_red[rl + 8], ps1);
            atomicAdd(&s_red[128 + rl + 8], pd1);
        }
    }
    __syncthreads();
    if (tid < 128) {
        g_as[row0 + tid] = s_red[tid];
        g_ad[row0 + tid] = s_red[128 + tid];
    }
}

// ------- aggregate: SMEM-broadcast (no shfl in hot loop), 8-deep gather MLP -------
__global__ void __launch_bounds__(256) k_agg(int l, const float* __restrict__ bias_l,
                                             float* __restrict__ outp) {
    __shared__ float2 swp[8][32];
    int d = (blockIdx.x * blockDim.x + threadIdx.x) >> 5;
    int lane = threadIdx.x & 31;
    int wid = (threadIdx.x >> 5) & 7;
    if (d >= NN) return;

    int beg = g_rowptr[d];
    int endE = g_rowptr[d + 1] - 1;   // real edges in [beg, endE); self-loop at endE
    float add = g_ad[d];
    float asd = g_as[d];
    const int4* ep = g_epk4;
    const uint2* h2 = (const uint2*)g_hh;

    float den = 0.f;
    float ssum = 0.f;
    float4 acc = make_float4(0.f, 0.f, 0.f, 0.f);

    for (int base = beg; base < endE; base += 32) {
        int j = base + lane;
        float ex = 0.f;
        int s = 0;
        if (j < endE) {
            int4 e = ep[j];
            s = e.x;
            int sbi = (l == 0) ? e.y : (l == 1) ? e.z : e.w;
            float sc = __int_as_float(sbi);
            ssum += sc;
            float al = g_as[s] + add + sc;
            al = al > 0.f ? al : 0.2f * al;
            ex = __expf(al);
        }
        den += ex;
        swp[wid][lane] = make_float2(ex, __int_as_float(s));
        __syncwarp();

        int cnt = endE - base;
        if (cnt > 32) cnt = 32;
        int t = 0;
        for (; t + 8 <= cnt; t += 8) {
            float2 p[8];
            #pragma unroll
            for (int q = 0; q < 8; q++) p[q] = swp[wid][t + q];
            uint2 rw[8];
            #pragma unroll
            for (int q = 0; q < 8; q++)
                rw[q] = h2[(size_t)__float_as_int(p[q].y) * 32 + lane];
            #pragma unroll
            for (int q = 0; q < 8; q++) {
                float2 v0 = __half22float2(*(__half2*)&rw[q].x);
                float2 v1 = __half22float2(*(__half2*)&rw[q].y);
                float e0 = p[q].x;
                acc.x = fmaf(e0, v0.x, acc.x);
                acc.y = fmaf(e0, v0.y, acc.y);
                acc.z = fmaf(e0, v1.x, acc.z);
                acc.w = fmaf(e0, v1.y, acc.w);
            }
        }
        for (; t < cnt; t++) {
            float2 p = swp[wid][t];
            uint2 r0 = h2[(size_t)__float_as_int(p.y) * 32 + lane];
            float2 v0 = __half22float2(*(__half2*)&r0.x);
            float2 v1 = __half22float2(*(__half2*)&r0.y);
            acc.x = fmaf(p.x, v0.x, acc.x);
            acc.y = fmaf(p.x, v0.y, acc.y);
            acc.z = fmaf(p.x, v1.x, acc.z);
            acc.w = fmaf(p.x, v1.y, acc.w);
        }
        __syncwarp();
    }
    #pragma unroll
    for (int o = 16; o; o >>= 1) {
        den += __shfl_xor_sync(0xffffffffu, den, o);
        ssum += __shfl_xor_sync(0xffffffffu, ssum, o);
    }

    // self-loop: score = mean of incoming scores (0 if none)
    float cf = fmaxf((float)(endE - beg), 1.0f);
    float als = asd + add + ssum / cf;
    als = als > 0.f ? als : 0.2f * als;
    float exs = __expf(als);
    den += exs;
    {
        uint2 raw = h2[(size_t)d * 32 + lane];
        float2 v0 = __half22float2(*(__half2*)&raw.x);
        float2 v1 = __half22float2(*(__half2*)&raw.y);
        acc.x = fmaf(exs, v0.x, acc.x);
        acc.y = fmaf(exs, v0.y, acc.y);
        acc.z = fmaf(exs, v1.x, acc.z);
        acc.w = fmaf(exs, v1.y, acc.w);
    }

    float r = 1.0f / den;
    float4 b4 = ((const float4*)bias_l)[lane];
    float4 o4;
    o4.x = gelu_f(fmaf(acc.x, r, b4.x));
    o4.y = gelu_f(fmaf(acc.y, r, b4.y));
    o4.z = gelu_f(fmaf(acc.z, r, b4.z));
    o4.w = gelu_f(fmaf(acc.w, r, b4.w));

    if (outp) {
        ((float4*)outp)[(size_t)d * 32 + lane] = o4;
    } else {
        __nv_bfloat16 h0 = __float2bfloat16_rn(o4.x), h1 = __float2bfloat16_rn(o4.y);
        __nv_bfloat16 h2b = __float2bfloat16_rn(o4.z), h3 = __float2bfloat16_rn(o4.w);
        __nv_bfloat162 ha, hb;
        ha.x = h0; ha.y = h1; hb.x = h2b; hb.y = h3;
        __nv_bfloat162 la = __floats2bfloat162_rn(o4.x - __bfloat162float(h0),
                                                  o4.y - __bfloat162float(h1));
        __nv_bfloat162 lb = __floats2bfloat162_rn(o4.z - __bfloat162float(h2b),
                                                  o4.w - __bfloat162float(h3));
        uint2 ph, pl;
        ph.x = *(unsigned*)&ha; ph.y = *(unsigned*)&hb;
        pl.x = *(unsigned*)&la; pl.y = *(unsigned*)&lb;
        ((uint2*)g_xh)[(size_t)d * 32 + lane] = ph;
        ((uint2*)g_xl)[(size_t)d * 32 + lane] = pl;
    }
}

// ---------------- launch ----------------
extern "C" void kernel_launch(void* const* d_in, const int* in_sizes, int n_in,
                              void* d_out, int out_size) {
    const float* x    = (const float*)d_in[0];
    const int*   ei   = (const int*)d_in[1];
    const float* ea   = (const float*)d_in[2];
    const float* Ws   = (const float*)d_in[3];
    const float* a_s  = (const float*)d_in[4];
    const float* a_d  = (const float*)d_in[5];
    const float* We   = (const float*)d_in[6];
    const float* ae   = (const float*)d_in[7];
    const float* bias = (const float*)d_in[8];
    float* out = (float*)d_out;

    const int SMEM_SZ = 4 * 128 * PK * 2;  // 139264 B
    cudaFuncSetAttribute(k_gemm_tc, cudaFuncAttributeMaxDynamicSharedMemorySize, SMEM_SZ);

    k_wsplit<<<449, 256>>>(Ws, We, ae);
    k_hist<<<NE / 256, 256>>>(ei);
    k_scan256<<<256, 256>>>();
    k_scatter<<<NE / 256, 256>>>(ei, ea);

    for (int l = 0; l < 3; l++) {
        const float* xin = (l == 0) ? x : nullptr;     // nullptr -> pre-split g_xh/g_xl
        k_gemm_tc<<<NN / 128, 256, SMEM_SZ>>>(xin, l, a_s + l * DD, a_d + l * DD);
        float* outl = (l == 2) ? out : nullptr;        // nullptr -> split store to g_xh/g_xl
        k_agg<<<NN / 8, 256>>>(l, bias + l * DD, outl);
    }
}

// round 17
// speedup vs baseline: 1.1709x; 1.0103x over previous
#include <cuda_runtime.h>
#include <cuda_bf16.h>
#include <cuda_fp16.h>
#include <stdint.h>
#include <math.h>

#define NN 65536
#define NE 524288
#define EX (NE + NN)
#define DD 128
#define PK 136   // padded k-dim (bf16 elems); 272B rows => ldmatrix conflict-free

// ---------------- scratch (device globals: allocation-free) ----------------
// NOTE zero-state invariant: g_cnt and g_bsum are zero at every kernel_launch entry.
// (zero-initialized at load; k_scan256 re-zeroes g_cnt after consuming it, k_scatter
//  re-zeroes g_bsum after scan consumed it — so each execution restores the invariant.)
__device__ __half g_hh[(size_t)NN * DD];           // 16MB: h in fp16 (agg gather path)
__device__ __nv_bfloat16 g_xh[(size_t)NN * DD];    // activations split hi
__device__ __nv_bfloat16 g_xl[(size_t)NN * DD];    // activations split lo
__device__ float g_as[NN];
__device__ float g_ad[NN];
__device__ int4  g_epk4[EX];                // packed (src, s0, s1, s2) per CSR slot
__device__ int   g_rowptr[NN + 1];
__device__ int   g_wslot[NN];
__device__ int   g_cnt[NN];
__device__ int   g_bsum[256];
__device__ float g_ve[3][32];
__device__ __nv_bfloat16 g_wh[3][DD * DD];   // W^T split hi (n-major)
__device__ __nv_bfloat16 g_wl[3][DD * DD];   // W^T split lo (n-major)

__device__ __forceinline__ float gelu_f(float x) {
    return 0.5f * x * (1.0f + erff(x * 0.7071067811865476f));
}

// ---------------- preprocessing ----------------
// blocks 0..191: split W -> bf16 hi/lo (transposed, n-major)
// block 192:     ve[l] = We[l] @ att_edge[l]
// blocks 193..2240: histogram of dst degrees (g_cnt pre-zeroed by invariant)
__global__ void k_wsplit_hist(const float* __restrict__ Ws,
                              const float* __restrict__ We, const float* __restrict__ ae,
                              const int* __restrict__ ei) {
    int b = blockIdx.x;
    if (b >= 193) {
        int e = (b - 193) * 256 + threadIdx.x;
        if (e < NE) atomicAdd(&g_cnt[ei[NE + e]], 1);
        return;
    }
    if (b == 192) {
        int t = threadIdx.x;
        if (t < 96) {
            int l = t / 32, k = t % 32;
            const float* w = We + l * 32 * DD + k * DD;
            const float* a = ae + l * DD;
            float s = 0.f;
            #pragma unroll 8
            for (int d = 0; d < DD; d++) s += w[d] * a[d];
            g_ve[l][k] = s;
        }
        return;
    }
    int idx = b * blockDim.x + threadIdx.x;   // 3*128*128
    int l = idx >> 14;
    int rem = idx & 16383;
    int k = rem >> 7, n = rem & 127;
    float v = Ws[idx];
    __nv_bfloat16 h = __float2bfloat16_rn(v);
    float lo = v - __bfloat162float(h);
    g_wh[l][n * DD + k] = h;
    g_wl[l][n * DD + k] = __float2bfloat16_rn(lo);
}

__global__ void __launch_bounds__(256) k_scan256() {
    __shared__ int ws[8], ws2[8], s_base;
    int b = blockIdx.x, t = threadIdx.x;
    int n = b * 256 + t;
    int lane = t & 31, w = t >> 5;
    int v = g_cnt[n] + 1;
    g_cnt[n] = 0;                        // restore zero-state invariant for next launch
    int x = v;
    #pragma unroll
    for (int o = 1; o < 32; o <<= 1) {
        int y = __shfl_up_sync(0xffffffffu, x, o);
        if (lane >= o) x += y;
    }
    if (lane == 31) ws[w] = x;
    __syncthreads();
    if (t < 8) {
        int s = ws[t];
        #pragma unroll
        for (int o = 1; o < 8; o <<= 1) {
            int y = __shfl_up_sync(0xffu, s, o);
            if (t >= o) s += y;
        }
        ws[t] = s;
    }
    __syncthreads();
    int intra = x - v + (w ? ws[w - 1] : 0);
    int total = ws[7];
    if (t == 0) atomicExch(&g_bsum[b], total);
    volatile int* vb = g_bsum;
    int av;
    while ((av = vb[t]) == 0) { }
    int contrib = (t < b) ? av : 0;
    #pragma unroll
    for (int o = 16; o; o >>= 1) contrib += __shfl_xor_sync(0xffffffffu, contrib, o);
    if (lane == 0) ws2[w] = contrib;
    __syncthreads();
    if (t == 0) {
        int s = 0;
        #pragma unroll
        for (int i = 0; i < 8; i++) s += ws2[i];
        s_base = s;
    }
    __syncthreads();
    int excl = s_base + intra;
    g_rowptr[n] = excl;
    g_wslot[n] = excl;
    if (n == NN - 1) g_rowptr[NN] = EX;
}

// warp handles 32 edges: coalesced 4KB attr load -> swizzled smem -> per-lane dots
__global__ void __launch_bounds__(256) k_scatter(const int* __restrict__ ei,
                                                 const float* __restrict__ ea) {
    __shared__ float sve[96];
    __shared__ __align__(16) char sbuf[8][4096];
    int tid = threadIdx.x;
    if (tid < 96) sve[tid] = ((const float*)g_ve)[tid];
    if (blockIdx.x == 0) g_bsum[tid] = 0;   // restore zero-state invariant (scan done)
    __syncthreads();
    int wid = tid >> 5, lane = tid & 31;
    int e = blockIdx.x * 256 + tid;
    int ebase = blockIdx.x * 256 + wid * 32;

    const float4* src = (const float4*)(ea + (size_t)ebase * 32);
    #pragma unroll
    for (int q = 0; q < 8; q++) {
        int idx = q * 32 + lane;
        uint32_t boff = (uint32_t)idx * 16u;
        uint32_t sw = boff ^ ((boff >> 3) & 0x70u);
        *(float4*)(sbuf[wid] + sw) = src[idx];
    }
    __syncwarp();

    float dot0 = 0.f, dot1 = 0.f, dot2 = 0.f;
    #pragma unroll
    for (int q = 0; q < 8; q++) {
        uint32_t boff = (uint32_t)lane * 128u + (uint32_t)q * 16u;
        uint32_t sw = boff ^ ((boff >> 3) & 0x70u);
        float4 v = *(const float4*)(sbuf[wid] + sw);
        const float* v0 = sve + 0 * 32 + q * 4;
        const float* v1 = sve + 1 * 32 + q * 4;
        const float* v2 = sve + 2 * 32 + q * 4;
        dot0 += v.x * v0[0] + v.y * v0[1] + v.z * v0[2] + v.w * v0[3];
        dot1 += v.x * v1[0] + v.y * v1[1] + v.z * v1[2] + v.w * v1[3];
        dot2 += v.x * v2[0] + v.y * v2[1] + v.z * v2[2] + v.w * v2[3];
    }

    int s = ei[e];
    int d = ei[NE + e];
    int p = atomicAdd(&g_wslot[d], 1);
    g_epk4[p] = make_int4(s, __float_as_int(dot0), __float_as_int(dot1), __float_as_int(dot2));
}

// ---------------- tensor-core GEMM + fused rowdots, fp16 h output ----------------
__device__ __forceinline__ void mma16816(float* c, const unsigned* a, const unsigned* b) {
    asm volatile(
        "mma.sync.aligned.m16n8k16.row.col.f32.bf16.bf16.f32 "
        "{%0,%1,%2,%3},{%4,%5,%6,%7},{%8,%9},{%0,%1,%2,%3};\n"
        : "+f"(c[0]), "+f"(c[1]), "+f"(c[2]), "+f"(c[3])
        : "r"(a[0]), "r"(a[1]), "r"(a[2]), "r"(a[3]), "r"(b[0]), "r"(b[1]));
}

__device__ __forceinline__ void ldm_x4(unsigned* r, unsigned addr) {
    asm volatile("ldmatrix.sync.aligned.m8n8.x4.shared.b16 {%0,%1,%2,%3},[%4];"
                 : "=r"(r[0]), "=r"(r[1]), "=r"(r[2]), "=r"(r[3]) : "r"(addr));
}

__device__ __forceinline__ void ldm_x2(unsigned* r, unsigned addr) {
    asm volatile("ldmatrix.sync.aligned.m8n8.x2.shared.b16 {%0,%1},[%2];"
                 : "=r"(r[0]), "=r"(r[1]) : "r"(addr));
}

extern __shared__ char smem_raw[];

__global__ void __launch_bounds__(256) k_gemm_tc(const float* __restrict__ Ain, int l,
                                                 const float* __restrict__ a_s,
                                                 const float* __restrict__ a_d) {
    __nv_bfloat16* sAh = (__nv_bfloat16*)smem_raw;
    __nv_bfloat16* sAl = sAh + 128 * PK;
    __nv_bfloat16* sBh = sAl + 128 * PK;
    __nv_bfloat16* sBl = sBh + 128 * PK;

    int tid = threadIdx.x;
    int row0 = blockIdx.x * 128;

    if (Ain) {
        const float4* A4 = (const float4*)(Ain + (size_t)row0 * DD);
        #pragma unroll
        for (int it = 0; it < 16; it++) {
            int idx = it * 256 + tid;
            int r = idx >> 5;
            int c = (idx & 31) << 2;
            float4 v = A4[idx];
            __nv_bfloat16 h0 = __float2bfloat16_rn(v.x), h1 = __float2bfloat16_rn(v.y);
            __nv_bfloat16 h2 = __float2bfloat16_rn(v.z), h3 = __float2bfloat16_rn(v.w);
            __nv_bfloat162 ha, hb, la, lb;
            ha.x = h0; ha.y = h1; hb.x = h2; hb.y = h3;
            la = __floats2bfloat162_rn(v.x - __bfloat162float(h0), v.y - __bfloat162float(h1));
            lb = __floats2bfloat162_rn(v.z - __bfloat162float(h2), v.w - __bfloat162float(h3));
            unsigned* dh = (unsigned*)(sAh + r * PK + c);
            unsigned* dl = (unsigned*)(sAl + r * PK + c);
            dh[0] = *(unsigned*)&ha; dh[1] = *(unsigned*)&hb;
            dl[0] = *(unsigned*)&la; dl[1] = *(unsigned*)&lb;
        }
    } else {
        const uint4* axh = (const uint4*)(g_xh + (size_t)row0 * DD);
        const uint4* axl = (const uint4*)(g_xl + (size_t)row0 * DD);
        #pragma unroll
        for (int it = 0; it < 8; it++) {
            int idx = it * 256 + tid;
            int r = idx >> 4;
            int kc = idx & 15;
            ((uint4*)(sAh + r * PK))[kc] = axh[idx];
            ((uint4*)(sAl + r * PK))[kc] = axl[idx];
        }
    }
    {
        const uint4* wh4 = (const uint4*)g_wh[l];
        const uint4* wl4 = (const uint4*)g_wl[l];
        #pragma unroll
        for (int it = 0; it < 8; it++) {
            int idx = it * 256 + tid;
            int n = idx >> 4;
            int kc = idx & 15;
            ((uint4*)(sBh + n * PK))[kc] = wh4[idx];
            ((uint4*)(sBl + n * PK))[kc] = wl4[idx];
        }
    }
    __syncthreads();

    int wid = tid >> 5, lane = tid & 31;
    int g = lane >> 2, tq = lane & 3;
    int wm = wid >> 2, wn = wid & 3;
    int mbase = wm * 64, nbase = wn * 32;

    unsigned baseAh, baseAl, baseBh, baseBl;
    {
        int aoff = ((mbase + (lane & 15)) * PK + ((lane >> 4) << 3)) * 2;
        baseAh = (unsigned)__cvta_generic_to_shared(sAh) + aoff;
        baseAl = (unsigned)__cvta_generic_to_shared(sAl) + aoff;
        int boff = ((nbase + (lane & 7)) * PK + (((lane >> 3) & 1) << 3)) * 2;
        baseBh = (unsigned)__cvta_generic_to_shared(sBh) + boff;
        baseBl = (unsigned)__cvta_generic_to_shared(sBl) + boff;
    }

    float acc[4][4][4];
    #pragma unroll
    for (int i = 0; i < 4; i++)
        #pragma unroll
        for (int j = 0; j < 4; j++)
            #pragma unroll
            for (int q = 0; q < 4; q++) acc[i][j][q] = 0.f;

    #pragma unroll
    for (int kk = 0; kk < 8; kk++) {
        unsigned kb = kk * 32;
        unsigned Ah[4][4], Al[4][4], Bh[4][2], Bl[4][2];
        #pragma unroll
        for (int i = 0; i < 4; i++) {
            unsigned off = (unsigned)(i * 16 * PK * 2) + kb;
            ldm_x4(Ah[i], baseAh + off);
            ldm_x4(Al[i], baseAl + off);
        }
        #pragma unroll
        for (int j = 0; j < 4; j++) {
            unsigned off = (unsigned)(j * 8 * PK * 2) + kb;
            ldm_x2(Bh[j], baseBh + off);
            ldm_x2(Bl[j], baseBl + off);
        }
        #pragma unroll
        for (int i = 0; i < 4; i++)
            #pragma unroll
            for (int j = 0; j < 4; j++) {
                mma16816(acc[i][j], Ah[i], Bh[j]);
                mma16816(acc[i][j], Al[i], Bh[j]);
                mma16816(acc[i][j], Ah[i], Bl[j]);
            }
    }

    // store h as fp16
    #pragma unroll
    for (int i = 0; i < 4; i++) {
        int r = row0 + mbase + i * 16 + g;
        #pragma unroll
        for (int j = 0; j < 4; j++) {
            int c = nbase + j * 8 + 2 * tq;
            *(__half2*)(g_hh + (size_t)r * DD + c) =
                __float22half2_rn(make_float2(acc[i][j][0], acc[i][j][1]));
            *(__half2*)(g_hh + (size_t)(r + 8) * DD + c) =
                __float22half2_rn(make_float2(acc[i][j][2], acc[i][j][3]));
        }
    }

    // fused rowdots
    float asv[4][2], adv[4][2];
    #pragma unroll
    for (int j = 0; j < 4; j++) {
        int c = nbase + j * 8 + 2 * tq;
        asv[j][0] = a_s[c]; asv[j][1] = a_s[c + 1];
        adv[j][0] = a_d[c]; adv[j][1] = a_d[c + 1];
    }
    __syncthreads();
    float* s_red = (float*)smem_raw;
    if (tid < 128) { s_red[tid] = 0.f; s_red[128 + tid] = 0.f; }
    __syncthreads();
    #pragma unroll
    for (int i = 0; i < 4; i++) {
        float ps0 = 0.f, pd0 = 0.f, ps1 = 0.f, pd1 = 0.f;
        #pragma unroll
        for (int j = 0; j < 4; j++) {
            ps0 += acc[i][j][0] * asv[j][0] + acc[i][j][1] * asv[j][1];
            pd0 += acc[i][j][0] * adv[j][0] + acc[i][j][1] * adv[j][1];
            ps1 += acc[i][j][2] * asv[j][0] + acc[i][j][3] * asv[j][1];
            pd1 += acc[i][j][2] * adv[j][0] + acc[i][j][3] * adv[j][1];
        }
        #pragma unroll
        for (int o = 1; o < 4; o <<= 1) {
            ps0 += __shfl_xor_sync(0xffffffffu, ps0, o);
            pd0 += __shfl_xor_sync(0xffffffffu, pd0, o);
            ps1 += __shfl_xor_sync(0xffffffffu, ps1, o);
            pd1 += __shfl_xor_sync(0xffffffffu, pd1, o);
        }
        if (tq == 0) {
            int rl = mbase + i * 16 + g;
            atomicAdd(&s_red[rl], ps0);
            atomicAdd(&s_red[128 + rl], pd0);
            atomicAdd(&s_red[rl + 8], ps1);
            atomicAdd(&s_red[128 + rl + 8], pd1);
        }
    }
    __syncthreads();
    if (tid < 128) {
        g_as[row0 + tid] = s_red[tid];
        g_ad[row0 + tid] = s_red[128 + tid];
    }
}

// ------- aggregate: SMEM-broadcast (no shfl in hot loop), 8-deep gather MLP -------
__global__ void __launch_bounds__(256) k_agg(int l, const float* __restrict__ bias_l,
                                             float* __restrict__ outp) {
    __shared__ float2 swp[8][32];
    int d = (blockIdx.x * blockDim.x + threadIdx.x) >> 5;
    int lane = threadIdx.x & 31;
    int wid = (threadIdx.x >> 5) & 7;
    if (d >= NN) return;

    int beg = g_rowptr[d];
    int endE = g_rowptr[d + 1] - 1;   // real edges in [beg, endE); self-loop at endE
    float add = g_ad[d];
    float asd = g_as[d];
    const int4* ep = g_epk4;
    const uint2* h2 = (const uint2*)g_hh;

    float den = 0.f;
    float ssum = 0.f;
    float4 acc = make_float4(0.f, 0.f, 0.f, 0.f);

    for (int base = beg; base < endE; base += 32) {
        int j = base + lane;
        float ex = 0.f;
        int s = 0;
        if (j < endE) {
            int4 e = ep[j];
            s = e.x;
            int sbi = (l == 0) ? e.y : (l == 1) ? e.z : e.w;
            float sc = __int_as_float(sbi);
            ssum += sc;
            float al = g_as[s] + add + sc;
            al = al > 0.f ? al : 0.2f * al;
            ex = __expf(al);
        }
        den += ex;
        swp[wid][lane] = make_float2(ex, __int_as_float(s));
        __syncwarp();

        int cnt = endE - base;
        if (cnt > 32) cnt = 32;
        int t = 0;
        for (; t + 8 <= cnt; t += 8) {
            float2 p[8];
            #pragma unroll
            for (int q = 0; q < 8; q++) p[q] = swp[wid][t + q];
            uint2 rw[8];
            #pragma unroll
            for (int q = 0; q < 8; q++)
                rw[q] = h2[(size_t)__float_as_int(p[q].y) * 32 + lane];
            #pragma unroll
            for (int q = 0; q < 8; q++) {
                float2 v0 = __half22float2(*(__half2*)&rw[q].x);
                float2 v1 = __half22float2(*(__half2*)&rw[q].y);
                float e0 = p[q].x;
                acc.x = fmaf(e0, v0.x, acc.x);
                acc.y = fmaf(e0, v0.y, acc.y);
                acc.z = fmaf(e0, v1.x, acc.z);
                acc.w = fmaf(e0, v1.y, acc.w);
            }
        }
        for (; t < cnt; t++) {
            float2 p = swp[wid][t];
            uint2 r0 = h2[(size_t)__float_as_int(p.y) * 32 + lane];
            float2 v0 = __half22float2(*(__half2*)&r0.x);
            float2 v1 = __half22float2(*(__half2*)&r0.y);
            acc.x = fmaf(p.x, v0.x, acc.x);
            acc.y = fmaf(p.x, v0.y, acc.y);
            acc.z = fmaf(p.x, v1.x, acc.z);
            acc.w = fmaf(p.x, v1.y, acc.w);
        }
        __syncwarp();
    }
    #pragma unroll
    for (int o = 16; o; o >>= 1) {
        den += __shfl_xor_sync(0xffffffffu, den, o);
        ssum += __shfl_xor_sync(0xffffffffu, ssum, o);
    }

    // self-loop: score = mean of incoming scores (0 if none)
    float cf = fmaxf((float)(endE - beg), 1.0f);
    float als = asd + add + ssum / cf;
    als = als > 0.f ? als : 0.2f * als;
    float exs = __expf(als);
    den += exs;
    {
        uint2 raw = h2[(size_t)d * 32 + lane];
        float2 v0 = __half22float2(*(__half2*)&raw.x);
        float2 v1 = __half22float2(*(__half2*)&raw.y);
        acc.x = fmaf(exs, v0.x, acc.x);
        acc.y = fmaf(exs, v0.y, acc.y);
        acc.z = fmaf(exs, v1.x, acc.z);
        acc.w = fmaf(exs, v1.y, acc.w);
    }

    float r = 1.0f / den;
    float4 b4 = ((const float4*)bias_l)[lane];
    float4 o4;
    o4.x = gelu_f(fmaf(acc.x, r, b4.x));
    o4.y = gelu_f(fmaf(acc.y, r, b4.y));
    o4.z = gelu_f(fmaf(acc.z, r, b4.z));
    o4.w = gelu_f(fmaf(acc.w, r, b4.w));

    if (outp) {
        ((float4*)outp)[(size_t)d * 32 + lane] = o4;
    } else {
        __nv_bfloat16 h0 = __float2bfloat16_rn(o4.x), h1 = __float2bfloat16_rn(o4.y);
        __nv_bfloat16 h2b = __float2bfloat16_rn(o4.z), h3 = __float2bfloat16_rn(o4.w);
        __nv_bfloat162 ha, hb;
        ha.x = h0; ha.y = h1; hb.x = h2b; hb.y = h3;
        __nv_bfloat162 la = __floats2bfloat162_rn(o4.x - __bfloat162float(h0),
                                                  o4.y - __bfloat162float(h1));
        __nv_bfloat162 lb = __floats2bfloat162_rn(o4.z - __bfloat162float(h2b),
                                                  o4.w - __bfloat162float(h3));
        uint2 ph, pl;
        ph.x = *(unsigned*)&ha; ph.y = *(unsigned*)&hb;
        pl.x = *(unsigned*)&la; pl.y = *(unsigned*)&lb;
        ((uint2*)g_xh)[(size_t)d * 32 + lane] = ph;
        ((uint2*)g_xl)[(size_t)d * 32 + lane] = pl;
    }
}

// ---------------- launch ----------------
extern "C" void kernel_launch(void* const* d_in, const int* in_sizes, int n_in,
                              void* d_out, int out_size) {
    const float* x    = (const float*)d_in[0];
    const int*   ei   = (const int*)d_in[1];
    const float* ea   = (const float*)d_in[2];
    const float* Ws   = (const float*)d_in[3];
    const float* a_s  = (const float*)d_in[4];
    const float* a_d  = (const float*)d_in[5];
    const float* We   = (const float*)d_in[6];
    const float* ae   = (const float*)d_in[7];
    const float* bias = (const float*)d_in[8];
    float* out = (float*)d_out;

    const int SMEM_SZ = 4 * 128 * PK * 2;  // 139264 B
    cudaFuncSetAttribute(k_gemm_tc, cudaFuncAttributeMaxDynamicSharedMemorySize, SMEM_SZ);

    k_wsplit_hist<<<193 + NE / 256, 256>>>(Ws, We, ae, ei);
    k_scan256<<<256, 256>>>();
    k_scatter<<<NE / 256, 256>>>(ei, ea);

    for (int l = 0; l < 3; l++) {
        const float* xin = (l == 0) ? x : nullptr;     // nullptr -> pre-split g_xh/g_xl
        k_gemm_tc<<<NN / 128, 256, SMEM_SZ>>>(xin, l, a_s + l * DD, a_d + l * DD);
        float* outl = (l == 2) ? out : nullptr;        // nullptr -> split store to g_xh/g_xl
        k_agg<<<NN / 8, 256>>>(l, bias + l * DD, outl);
    }
}